// round 11
// baseline (speedup 1.0000x reference)
#include <cuda_runtime.h>
#include <math.h>

#define HW 128
#define NPIX (HW*HW)
#define NF 512
#define NP 256
#define SIGMAINV 7000.0f
#define BBOX_M 0.06f
#define DLB_T 0.055f
#define PATCH_R 0.0605f   /* >= half-diagonal of 8x4 pixel-center patch (0.0595) */

__device__ __forceinline__ float seg_d2(float px, float py, float ax, float ay,
                                        float bx, float by) {
    float abx = bx - ax, aby = by - ay;
    float apx = px - ax, apy = py - ay;
    float t = __fdividef(apx * abx + apy * aby, abx * abx + aby * aby + 1e-10f);
    t = fminf(fmaxf(t, 0.0f), 1.0f);
    float dx = apx - t * abx;
    float dy = apy - t * aby;
    return dx * dx + dy * dy;
}

// Single fused kernel. Block = 256 threads = 8 warps = one 8x4-pixel patch.
// Phase 0: block-local preprocessing into SMEM; ballot combines bbox test
//          with a conservative Lipschitz distance pre-cull at patch center.
// Phase 1: deterministic compaction of survivors into s_list.
// Phase 2: warps take list entries round-robin, software-pipelined; z path
//          and edge path each behind one warp-uniform branch.
// Phase 3: smem reduction; warp 0 gathers winner colors + writes.
__global__ __launch_bounds__(256)
void raster_fused(float* __restrict__ out,
                  const float* __restrict__ pts,
                  const float* __restrict__ cols,
                  const float* __restrict__ rot,
                  const float* __restrict__ cpos,
                  const float* __restrict__ proj,
                  const int* __restrict__ faces) {
    __shared__ float s_vx[NP], s_vy[NP], s_cx[NP], s_cy[NP], s_cz[NP];
    __shared__ float4 s_A[NF];   // x0,y0,x1,y1
    __shared__ float4 s_B[NF];   // x2,y2,invden,h0
    __shared__ float4 s_C[NF];   // h1,h2,z0,z1
    __shared__ float s_z2[NF];
    __shared__ unsigned s_words[16];
    __shared__ int s_cnt;
    __shared__ short s_list[NF];
    __shared__ float s_rz[8][32], s_rw0[8][32], s_rw1[8][32], s_rw2[8][32], s_rp[8][32];
    __shared__ int s_rf[8][32];

    int t = threadIdx.x;
    int lane = t & 31;
    int wid = t >> 5;
    int b = blockIdx.x;
    int px0 = (b & 15) * 8;     // 16 patches across
    int py0 = (b >> 4) * 4;     // 32 patch-rows
    int ix = px0 + (lane & 7);
    int iy = py0 + (lane >> 3);

    float px = (ix + 0.5f) * (2.0f / HW) - 1.0f;
    float py = 1.0f - (iy + 0.5f) * (2.0f / HW);

    // patch NDC bounds (pixel centers) + patch center
    float xmn = (px0 + 0.5f) * (2.0f / HW) - 1.0f;
    float xmx = (px0 + 7.5f) * (2.0f / HW) - 1.0f;
    float ymx = 1.0f - (py0 + 0.5f) * (2.0f / HW);
    float ymn = 1.0f - (py0 + 3.5f) * (2.0f / HW);
    float pcx = (px0 + 4.0f) * (2.0f / HW) - 1.0f;
    float pcy = 1.0f - (py0 + 2.0f) * (2.0f / HW);

    // ---- Phase 0a: per-vertex transform (1 vertex / thread) ----
    {
        float r00 = rot[0], r01 = rot[1], r02 = rot[2];
        float r10 = rot[3], r11 = rot[4], r12 = rot[5];
        float r20 = rot[6], r21 = rot[7], r22 = rot[8];
        float cx = cpos[0], cy = cpos[1], cz = cpos[2];
        float pr0 = proj[0], pr1 = proj[1], pr2 = proj[2];

        float qx = pts[t * 3 + 0] - cx;
        float qy = pts[t * 3 + 1] - cy;
        float qz = pts[t * 3 + 2] - cz;
        float X = qx * r00 + qy * r01 + qz * r02;
        float Y = qx * r10 + qy * r11 + qz * r12;
        float Z = qx * r20 + qy * r21 + qz * r22;
        s_cx[t] = X; s_cy[t] = Y; s_cz[t] = Z;
        s_vx[t] = (X * pr0) / (Z * pr2);
        s_vy[t] = (Y * pr1) / (Z * pr2);
    }
    __syncthreads();

    // ---- Phase 0b: per-face tables (2 faces / thread) + cull ballot ----
#pragma unroll
    for (int i = 0; i < 2; i++) {
        int f = i * 256 + t;   // == i*256 + wid*32 + lane
        int i0 = faces[f * 3 + 0];
        int i1 = faces[f * 3 + 1];
        int i2 = faces[f * 3 + 2];
        float x0 = s_vx[i0], y0 = s_vy[i0];
        float x1 = s_vx[i1], y1 = s_vy[i1];
        float x2 = s_vx[i2], y2 = s_vy[i2];

        // normal z in camera space (only x,y components of edges needed)
        float e1x = s_cx[i1] - s_cx[i0], e1y = s_cy[i1] - s_cy[i0];
        float e2x = s_cx[i2] - s_cx[i0], e2y = s_cy[i2] - s_cy[i0];
        float nz = e1x * e2y - e1y * e2x;

        float area = (x1 - x0) * (y2 - y0) - (x2 - x0) * (y1 - y0);
        bool ok = (nz > 0.0f) && (fabsf(area) > 1e-10f);
        float invden = ok ? (1.0f / area) : 0.0f;

        // margin bbox test
        float bxm = fminf(fminf(x0, x1), x2) - BBOX_M;
        float bxM = fmaxf(fmaxf(x0, x1), x2) + BBOX_M;
        float bym = fminf(fminf(y0, y1), y2) - BBOX_M;
        float byM = fmaxf(fmaxf(y0, y1), y2) + BBOX_M;
        bool ov = ok && (bxm <= xmx) && (bxM >= xmn) && (bym <= ymx) && (byM >= ymn);

        float aabs = fabsf(area);
        float L0s = (x2 - x1) * (x2 - x1) + (y2 - y1) * (y2 - y1);
        float L1s = (x0 - x2) * (x0 - x2) + (y0 - y2) * (y0 - y2);
        float L2s = (x1 - x0) * (x1 - x0) + (y1 - y0) * (y1 - y0);
        float h0 = aabs * rsqrtf(fmaxf(L0s, 1e-40f));
        float h1 = aabs * rsqrtf(fmaxf(L1s, 1e-40f));
        float h2 = aabs * rsqrtf(fmaxf(L2s, 1e-40f));

        // Lipschitz pre-cull: dlb is a max of signed edge-line distances,
        // 1-Lipschitz in position. If dlb(center) >= DLB_T + PATCH_R then
        // every patch pixel has dlb >= DLB_T (edge factor exactly 1.0) and
        // none is inside (inside => dlb <= 0 => dlb(center) <= PATCH_R).
        if (ov) {
            float w0c = ((x1 - pcx) * (y2 - pcy) - (x2 - pcx) * (y1 - pcy)) * invden;
            float w1c = ((x2 - pcx) * (y0 - pcy) - (x0 - pcx) * (y2 - pcy)) * invden;
            float w2c = 1.0f - w0c - w1c;
            float dlbc = fmaxf(fmaxf(-w0c * h0, -w1c * h1), -w2c * h2);
            ov = dlbc < (DLB_T + PATCH_R);
        }
        unsigned bal = __ballot_sync(0xFFFFFFFFu, ov);
        if (lane == 0) s_words[i * 8 + wid] = bal;

        s_A[f] = make_float4(x0, y0, x1, y1);
        s_B[f] = make_float4(x2, y2, invden, h0);
        s_C[f] = make_float4(h1, h2, s_cz[i0], s_cz[i1]);
        s_z2[f] = s_cz[i2];

        // block 0 additionally writes the normalized normals output
        if (b == 0) {
            float e1z = s_cz[i1] - s_cz[i0];
            float e2z = s_cz[i2] - s_cz[i0];
            float nxx = e1y * e2z - e1z * e2y;
            float nyy = e1z * e2x - e1x * e2z;
            float nlen = sqrtf(nxx * nxx + nyy * nyy + nz * nz + 1e-8f);
            float ninv = 1.0f / (nlen + 1e-15f);
            out[NPIX * 4 + f * 3 + 0] = nxx * ninv;
            out[NPIX * 4 + f * 3 + 1] = nyy * ninv;
            out[NPIX * 4 + f * 3 + 2] = nz * ninv;
        }
    }
    __syncthreads();

    // ---- Phase 1: deterministic compaction by warp 0 ----
    if (wid == 0) {
        unsigned wv = (lane < 16) ? s_words[lane] : 0u;
        int c = __popc(wv);
        int s = c;
#pragma unroll
        for (int off = 1; off < 32; off <<= 1) {
            int n = __shfl_up_sync(0xFFFFFFFFu, s, off);
            if (lane >= off) s += n;
        }
        if (lane == 15) s_cnt = s;
        if (lane < 16) {
            int pos = s - c;
            int base = lane * 32;
            unsigned m = wv;
            while (m) {
                int bit = __ffs(m) - 1;
                m &= m - 1;
                s_list[pos++] = (short)(base + bit);
            }
        }
    }
    __syncthreads();

    int cnt = s_cnt;
    float prodv = 1.0f;
    float zb = 3.0e38f;
    float w0b = 0.0f, w1b = 0.0f, w2b = 0.0f;
    int fb = 0x7FFFFFFF;

    // ---- Phase 2: balanced, software-pipelined, predicated face loop ----
    int j = wid;
    int f = -1;
    float4 A, B, C;
    float z2v;
    if (j < cnt) {
        f = s_list[j];
        A = s_A[f]; B = s_B[f]; C = s_C[f]; z2v = s_z2[f];
    }
#pragma unroll 1
    while (f >= 0) {
        // prefetch next face while current computes
        int jn = j + 8;
        int fn = -1;
        float4 An, Bn, Cn;
        float z2n;
        if (jn < cnt) {
            fn = s_list[jn];
            An = s_A[fn]; Bn = s_B[fn]; Cn = s_C[fn]; z2n = s_z2[fn];
        }

        float w0 = ((A.z - px) * (B.y - py) - (B.x - px) * (A.w - py)) * B.z;
        float w1 = ((B.x - px) * (A.y - py) - (A.x - px) * (B.y - py)) * B.z;
        float w2 = 1.0f - w0 - w1;
        bool inside = (w0 >= 0.0f) && (w1 >= 0.0f) && (w2 >= 0.0f);

        if (__any_sync(0xFFFFFFFFu, inside)) {
            float z = w0 * C.z + w1 * C.w + w2 * z2v;
            // argmin-first semantics: smaller z, ties -> smaller face index
            bool better = inside && (z < zb || (z == zb && f < fb));
            zb  = better ? z  : zb;
            fb  = better ? f  : fb;
            w0b = better ? w0 : w0b;
            w1b = better ? w1 : w1b;
            w2b = better ? w2 : w2b;
            prodv = inside ? 0.0f : prodv;   // probf = 1 inside
        }

        // lower bound on distance; if >= DLB_T, (1-probf)==1.0f exactly
        float dlb = fmaxf(fmaxf(-w0 * B.w, -w1 * C.x), -w2 * C.y);
        bool need = (!inside) && (prodv != 0.0f) && (dlb < DLB_T);
        if (__any_sync(0xFFFFFFFFu, need)) {
            float d2 = seg_d2(px, py, A.x, A.y, A.z, A.w);
            d2 = fminf(d2, seg_d2(px, py, A.z, A.w, B.x, B.y));
            d2 = fminf(d2, seg_d2(px, py, B.x, B.y, A.x, A.y));
            float e = __expf(-d2 * SIGMAINV);
            prodv = need ? prodv * (1.0f - e) : prodv;
        }

        j = jn; f = fn; A = An; B = Bn; C = Cn; z2v = z2n;
    }

    // ---- Phase 3: combine the 8 per-warp partials (lane = pixel) ----
    s_rz[wid][lane] = zb;
    s_rf[wid][lane] = fb;
    s_rw0[wid][lane] = w0b;
    s_rw1[wid][lane] = w1b;
    s_rw2[wid][lane] = w2b;
    s_rp[wid][lane] = prodv;
    __syncthreads();

    if (wid == 0) {
#pragma unroll
        for (int k = 1; k < 8; k++) {
            float oz = s_rz[k][lane];
            int of = s_rf[k][lane];
            prodv *= s_rp[k][lane];
            if (oz < zb || (oz == zb && of < fb)) {
                zb = oz; fb = of;
                w0b = s_rw0[k][lane];
                w1b = s_rw1[k][lane];
                w2b = s_rw2[k][lane];
            }
        }

        float rr = 0.0f, gg = 0.0f, bc = 0.0f;
        if (fb != 0x7FFFFFFF) {
            int i0 = faces[fb * 3 + 0];
            int i1 = faces[fb * 3 + 1];
            int i2 = faces[fb * 3 + 2];
            rr = w0b * cols[i0 * 3 + 0] + w1b * cols[i1 * 3 + 0] + w2b * cols[i2 * 3 + 0];
            gg = w0b * cols[i0 * 3 + 1] + w1b * cols[i1 * 3 + 1] + w2b * cols[i2 * 3 + 1];
            bc = w0b * cols[i0 * 3 + 2] + w1b * cols[i1 * 3 + 2] + w2b * cols[i2 * 3 + 2];
        }

        int p = iy * HW + ix;
        out[p * 3 + 0] = rr;
        out[p * 3 + 1] = gg;
        out[p * 3 + 2] = bc;
        out[NPIX * 3 + p] = 1.0f - prodv;
    }
}

extern "C" void kernel_launch(void* const* d_in, const int* in_sizes, int n_in,
                              void* d_out, int out_size) {
    const float* pts  = (const float*)d_in[0];
    const float* cols = (const float*)d_in[1];
    const float* rot  = (const float*)d_in[2];
    const float* cpos = (const float*)d_in[3];
    const float* proj = (const float*)d_in[4];
    const int*   fcs  = (const int*)d_in[5];
    float* out = (float*)d_out;

    raster_fused<<<NPIX / 32, 256>>>(out, pts, cols, rot, cpos, proj, fcs);
}

// round 12
// speedup vs baseline: 1.0226x; 1.0226x over previous
#include <cuda_runtime.h>
#include <math.h>

#define HW 128
#define NPIX (HW*HW)
#define NF 512
#define NP 256
#define SIGMAINV 7000.0f
#define BBOX_M 0.06f
#define DLB_T 0.055f
#define PATCH_R 0.0605f   /* >= half-diagonal of 8x4 pixel-center patch (0.0595) */

__device__ __forceinline__ float seg_d2(float px, float py, float ax, float ay,
                                        float bx, float by) {
    float abx = bx - ax, aby = by - ay;
    float apx = px - ax, apy = py - ay;
    float t = __fdividef(apx * abx + apy * aby, abx * abx + aby * aby + 1e-10f);
    t = fminf(fmaxf(t, 0.0f), 1.0f);
    float dx = apx - t * abx;
    float dy = apy - t * aby;
    return dx * dx + dy * dy;
}

// Single fused kernel. Block = 256 threads = 8 warps = one 8x4-pixel patch.
// Phase 0: block-local preprocessing into SMEM; ballot combines bbox test
//          with a conservative Lipschitz distance pre-cull at patch center.
// Phase 1: deterministic compaction of survivors into s_list.
// Phase 2: warps take list entries round-robin, software-pipelined; z path
//          and edge path each behind one warp-uniform branch.
// Phase 3: smem reduction; warp 0 gathers winner colors + writes.
__global__ __launch_bounds__(256)
void raster_fused(float* __restrict__ out,
                  const float* __restrict__ pts,
                  const float* __restrict__ cols,
                  const float* __restrict__ rot,
                  const float* __restrict__ cpos,
                  const float* __restrict__ proj,
                  const int* __restrict__ faces) {
    __shared__ float s_vx[NP], s_vy[NP], s_cx[NP], s_cy[NP], s_cz[NP];
    __shared__ float4 s_A[NF];   // x0,y0,x1,y1
    __shared__ float4 s_B[NF];   // x2,y2,invden,h0
    __shared__ float4 s_C[NF];   // h1,h2,z0,z1
    __shared__ float s_z2[NF];
    __shared__ unsigned s_words[16];
    __shared__ int s_cnt;
    __shared__ short s_list[NF];
    __shared__ float s_rz[8][32], s_rw0[8][32], s_rw1[8][32], s_rw2[8][32], s_rp[8][32];
    __shared__ int s_rf[8][32];

    int t = threadIdx.x;
    int lane = t & 31;
    int wid = t >> 5;
    int b = blockIdx.x;
    int px0 = (b & 15) * 8;     // 16 patches across
    int py0 = (b >> 4) * 4;     // 32 patch-rows
    int ix = px0 + (lane & 7);
    int iy = py0 + (lane >> 3);

    float px = (ix + 0.5f) * (2.0f / HW) - 1.0f;
    float py = 1.0f - (iy + 0.5f) * (2.0f / HW);

    // patch NDC bounds (pixel centers) + patch center
    float xmn = (px0 + 0.5f) * (2.0f / HW) - 1.0f;
    float xmx = (px0 + 7.5f) * (2.0f / HW) - 1.0f;
    float ymx = 1.0f - (py0 + 0.5f) * (2.0f / HW);
    float ymn = 1.0f - (py0 + 3.5f) * (2.0f / HW);
    float pcx = (px0 + 4.0f) * (2.0f / HW) - 1.0f;
    float pcy = 1.0f - (py0 + 2.0f) * (2.0f / HW);

    // ---- Phase 0a: per-vertex transform (1 vertex / thread) ----
    {
        float r00 = rot[0], r01 = rot[1], r02 = rot[2];
        float r10 = rot[3], r11 = rot[4], r12 = rot[5];
        float r20 = rot[6], r21 = rot[7], r22 = rot[8];
        float cx = cpos[0], cy = cpos[1], cz = cpos[2];
        float pr0 = proj[0], pr1 = proj[1], pr2 = proj[2];

        float qx = pts[t * 3 + 0] - cx;
        float qy = pts[t * 3 + 1] - cy;
        float qz = pts[t * 3 + 2] - cz;
        float X = qx * r00 + qy * r01 + qz * r02;
        float Y = qx * r10 + qy * r11 + qz * r12;
        float Z = qx * r20 + qy * r21 + qz * r22;
        s_cx[t] = X; s_cy[t] = Y; s_cz[t] = Z;
        s_vx[t] = (X * pr0) / (Z * pr2);
        s_vy[t] = (Y * pr1) / (Z * pr2);
    }
    __syncthreads();

    // ---- Phase 0b: per-face tables (2 faces / thread) + cull ballot ----
#pragma unroll
    for (int i = 0; i < 2; i++) {
        int f = i * 256 + t;   // == i*256 + wid*32 + lane
        int i0 = faces[f * 3 + 0];
        int i1 = faces[f * 3 + 1];
        int i2 = faces[f * 3 + 2];
        float x0 = s_vx[i0], y0 = s_vy[i0];
        float x1 = s_vx[i1], y1 = s_vy[i1];
        float x2 = s_vx[i2], y2 = s_vy[i2];

        // normal z in camera space (only x,y components of edges needed)
        float e1x = s_cx[i1] - s_cx[i0], e1y = s_cy[i1] - s_cy[i0];
        float e2x = s_cx[i2] - s_cx[i0], e2y = s_cy[i2] - s_cy[i0];
        float nz = e1x * e2y - e1y * e2x;

        float area = (x1 - x0) * (y2 - y0) - (x2 - x0) * (y1 - y0);
        bool ok = (nz > 0.0f) && (fabsf(area) > 1e-10f);
        float invden = ok ? (1.0f / area) : 0.0f;

        // margin bbox test
        float bxm = fminf(fminf(x0, x1), x2) - BBOX_M;
        float bxM = fmaxf(fmaxf(x0, x1), x2) + BBOX_M;
        float bym = fminf(fminf(y0, y1), y2) - BBOX_M;
        float byM = fmaxf(fmaxf(y0, y1), y2) + BBOX_M;
        bool ov = ok && (bxm <= xmx) && (bxM >= xmn) && (bym <= ymx) && (byM >= ymn);

        float aabs = fabsf(area);
        float L0s = (x2 - x1) * (x2 - x1) + (y2 - y1) * (y2 - y1);
        float L1s = (x0 - x2) * (x0 - x2) + (y0 - y2) * (y0 - y2);
        float L2s = (x1 - x0) * (x1 - x0) + (y1 - y0) * (y1 - y0);
        float h0 = aabs * rsqrtf(fmaxf(L0s, 1e-40f));
        float h1 = aabs * rsqrtf(fmaxf(L1s, 1e-40f));
        float h2 = aabs * rsqrtf(fmaxf(L2s, 1e-40f));

        // Lipschitz pre-cull: dlb is a max of signed edge-line distances,
        // 1-Lipschitz in position. If dlb(center) >= DLB_T + PATCH_R then
        // every patch pixel has dlb >= DLB_T (edge factor exactly 1.0) and
        // none is inside (inside => dlb <= 0 => dlb(center) <= PATCH_R).
        if (ov) {
            float w0c = ((x1 - pcx) * (y2 - pcy) - (x2 - pcx) * (y1 - pcy)) * invden;
            float w1c = ((x2 - pcx) * (y0 - pcy) - (x0 - pcx) * (y2 - pcy)) * invden;
            float w2c = 1.0f - w0c - w1c;
            float dlbc = fmaxf(fmaxf(-w0c * h0, -w1c * h1), -w2c * h2);
            ov = dlbc < (DLB_T + PATCH_R);
        }
        unsigned bal = __ballot_sync(0xFFFFFFFFu, ov);
        if (lane == 0) s_words[i * 8 + wid] = bal;

        s_A[f] = make_float4(x0, y0, x1, y1);
        s_B[f] = make_float4(x2, y2, invden, h0);
        s_C[f] = make_float4(h1, h2, s_cz[i0], s_cz[i1]);
        s_z2[f] = s_cz[i2];

        // block 0 additionally writes the normalized normals output
        if (b == 0) {
            float e1z = s_cz[i1] - s_cz[i0];
            float e2z = s_cz[i2] - s_cz[i0];
            float nxx = e1y * e2z - e1z * e2y;
            float nyy = e1z * e2x - e1x * e2z;
            float nlen = sqrtf(nxx * nxx + nyy * nyy + nz * nz + 1e-8f);
            float ninv = 1.0f / (nlen + 1e-15f);
            out[NPIX * 4 + f * 3 + 0] = nxx * ninv;
            out[NPIX * 4 + f * 3 + 1] = nyy * ninv;
            out[NPIX * 4 + f * 3 + 2] = nz * ninv;
        }
    }
    __syncthreads();

    // ---- Phase 1: deterministic compaction by warp 0 ----
    if (wid == 0) {
        unsigned wv = (lane < 16) ? s_words[lane] : 0u;
        int c = __popc(wv);
        int s = c;
#pragma unroll
        for (int off = 1; off < 32; off <<= 1) {
            int n = __shfl_up_sync(0xFFFFFFFFu, s, off);
            if (lane >= off) s += n;
        }
        if (lane == 15) s_cnt = s;
        if (lane < 16) {
            int pos = s - c;
            int base = lane * 32;
            unsigned m = wv;
            while (m) {
                int bit = __ffs(m) - 1;
                m &= m - 1;
                s_list[pos++] = (short)(base + bit);
            }
        }
    }
    __syncthreads();

    int cnt = s_cnt;
    float prodv = 1.0f;
    float zb = 3.0e38f;
    float w0b = 0.0f, w1b = 0.0f, w2b = 0.0f;
    int fb = 0x7FFFFFFF;

    // ---- Phase 2: balanced, software-pipelined, predicated face loop ----
    int j = wid;
    int f = -1;
    float4 A, B, C;
    float z2v;
    if (j < cnt) {
        f = s_list[j];
        A = s_A[f]; B = s_B[f]; C = s_C[f]; z2v = s_z2[f];
    }
#pragma unroll 1
    while (f >= 0) {
        // prefetch next face while current computes
        int jn = j + 8;
        int fn = -1;
        float4 An, Bn, Cn;
        float z2n;
        if (jn < cnt) {
            fn = s_list[jn];
            An = s_A[fn]; Bn = s_B[fn]; Cn = s_C[fn]; z2n = s_z2[fn];
        }

        float w0 = ((A.z - px) * (B.y - py) - (B.x - px) * (A.w - py)) * B.z;
        float w1 = ((B.x - px) * (A.y - py) - (A.x - px) * (B.y - py)) * B.z;
        float w2 = 1.0f - w0 - w1;
        bool inside = (w0 >= 0.0f) && (w1 >= 0.0f) && (w2 >= 0.0f);

        if (__any_sync(0xFFFFFFFFu, inside)) {
            float z = w0 * C.z + w1 * C.w + w2 * z2v;
            // argmin-first semantics: smaller z, ties -> smaller face index
            bool better = inside && (z < zb || (z == zb && f < fb));
            zb  = better ? z  : zb;
            fb  = better ? f  : fb;
            w0b = better ? w0 : w0b;
            w1b = better ? w1 : w1b;
            w2b = better ? w2 : w2b;
            prodv = inside ? 0.0f : prodv;   // probf = 1 inside
        }

        // lower bound on distance; if >= DLB_T, (1-probf)==1.0f exactly
        float dlb = fmaxf(fmaxf(-w0 * B.w, -w1 * C.x), -w2 * C.y);
        bool need = (!inside) && (prodv != 0.0f) && (dlb < DLB_T);
        if (__any_sync(0xFFFFFFFFu, need)) {
            float d2 = seg_d2(px, py, A.x, A.y, A.z, A.w);
            d2 = fminf(d2, seg_d2(px, py, A.z, A.w, B.x, B.y));
            d2 = fminf(d2, seg_d2(px, py, B.x, B.y, A.x, A.y));
            float e = __expf(-d2 * SIGMAINV);
            prodv = need ? prodv * (1.0f - e) : prodv;
        }

        j = jn; f = fn; A = An; B = Bn; C = Cn; z2v = z2n;
    }

    // ---- Phase 3: combine the 8 per-warp partials (lane = pixel) ----
    s_rz[wid][lane] = zb;
    s_rf[wid][lane] = fb;
    s_rw0[wid][lane] = w0b;
    s_rw1[wid][lane] = w1b;
    s_rw2[wid][lane] = w2b;
    s_rp[wid][lane] = prodv;
    __syncthreads();

    if (wid == 0) {
#pragma unroll
        for (int k = 1; k < 8; k++) {
            float oz = s_rz[k][lane];
            int of = s_rf[k][lane];
            prodv *= s_rp[k][lane];
            if (oz < zb || (oz == zb && of < fb)) {
                zb = oz; fb = of;
                w0b = s_rw0[k][lane];
                w1b = s_rw1[k][lane];
                w2b = s_rw2[k][lane];
            }
        }

        float rr = 0.0f, gg = 0.0f, bc = 0.0f;
        if (fb != 0x7FFFFFFF) {
            int i0 = faces[fb * 3 + 0];
            int i1 = faces[fb * 3 + 1];
            int i2 = faces[fb * 3 + 2];
            rr = w0b * cols[i0 * 3 + 0] + w1b * cols[i1 * 3 + 0] + w2b * cols[i2 * 3 + 0];
            gg = w0b * cols[i0 * 3 + 1] + w1b * cols[i1 * 3 + 1] + w2b * cols[i2 * 3 + 1];
            bc = w0b * cols[i0 * 3 + 2] + w1b * cols[i1 * 3 + 2] + w2b * cols[i2 * 3 + 2];
        }

        int p = iy * HW + ix;
        out[p * 3 + 0] = rr;
        out[p * 3 + 1] = gg;
        out[p * 3 + 2] = bc;
        out[NPIX * 3 + p] = 1.0f - prodv;
    }
}

extern "C" void kernel_launch(void* const* d_in, const int* in_sizes, int n_in,
                              void* d_out, int out_size) {
    const float* pts  = (const float*)d_in[0];
    const float* cols = (const float*)d_in[1];
    const float* rot  = (const float*)d_in[2];
    const float* cpos = (const float*)d_in[3];
    const float* proj = (const float*)d_in[4];
    const int*   fcs  = (const int*)d_in[5];
    float* out = (float*)d_out;

    raster_fused<<<NPIX / 32, 256>>>(out, pts, cols, rot, cpos, proj, fcs);
}